// round 1
// baseline (speedup 1.0000x reference)
#include <cuda_runtime.h>
#include <math.h>

#define Bsz   8
#define Tlen  1024
#define Cdim  768
#define Hn    12
#define Dh    64
#define BT    (Bsz * Tlen)     // 8192
#define C3    (3 * Cdim)       // 2304
#define BH    (Bsz * Hn)       // 96

// Scratch (device globals; no cudaMalloc allowed)
__device__ float g_qkv[BT * C3];            // 8192 x 2304
__device__ float g_q[BH * Tlen * Dh];       // [B*H, T, D] after RoPE
__device__ float g_k[BH * Tlen * Dh];
__device__ float g_v[BH * Tlen * Dh];
__device__ float g_y[BT * Cdim];            // attention output, [B*T, C]

// ---------------------------------------------------------------------------
// SGEMM with bias: C = A(MxK) @ B(KxN) + bias(N). Row-major. 128x128x8 tiles,
// 256 threads, 8x8 microtile per thread. M%128==0, N%128==0, K%8==0 assumed.
// ---------------------------------------------------------------------------
__global__ __launch_bounds__(256) void sgemm_bias(
    const float* __restrict__ A, const float* __restrict__ B,
    const float* __restrict__ bias, float* __restrict__ Cmat,
    int M, int N, int K)
{
    __shared__ float As[8][128];
    __shared__ float Bs[8][128];

    const int tid  = threadIdx.x;
    const int brow = blockIdx.y * 128;
    const int bcol = blockIdx.x * 128;

    // A-tile loader: 128 rows x 8 cols = 256 float4 (one per thread)
    const int a_row = tid >> 1;
    const int a_c4  = (tid & 1) * 4;
    // B-tile loader: 8 rows x 128 cols = 256 float4 (one per thread)
    const int b_row = tid >> 5;
    const int b_c4  = (tid & 31) * 4;

    const int ty = tid >> 4;   // 0..15 -> row group
    const int tx = tid & 15;   // 0..15 -> col group

    float acc[8][8];
    #pragma unroll
    for (int i = 0; i < 8; ++i)
        #pragma unroll
        for (int j = 0; j < 8; ++j) acc[i][j] = 0.f;

    const float* Aptr = A + (size_t)(brow + a_row) * K + a_c4;
    const float* Bptr = B + (size_t)b_row * N + bcol + b_c4;

    for (int k0 = 0; k0 < K; k0 += 8) {
        float4 av = *(const float4*)(Aptr + k0);
        float4 bv = *(const float4*)(Bptr + (size_t)k0 * N);
        As[a_c4 + 0][a_row] = av.x;
        As[a_c4 + 1][a_row] = av.y;
        As[a_c4 + 2][a_row] = av.z;
        As[a_c4 + 3][a_row] = av.w;
        *(float4*)&Bs[b_row][b_c4] = bv;
        __syncthreads();

        #pragma unroll
        for (int kk = 0; kk < 8; ++kk) {
            float ra[8], rb[8];
            #pragma unroll
            for (int i = 0; i < 8; ++i) ra[i] = As[kk][ty * 8 + i];
            #pragma unroll
            for (int j = 0; j < 8; ++j) rb[j] = Bs[kk][tx * 8 + j];
            #pragma unroll
            for (int i = 0; i < 8; ++i)
                #pragma unroll
                for (int j = 0; j < 8; ++j)
                    acc[i][j] = fmaf(ra[i], rb[j], acc[i][j]);
        }
        __syncthreads();
    }

    #pragma unroll
    for (int i = 0; i < 8; ++i) {
        const int r = brow + ty * 8 + i;
        #pragma unroll
        for (int j = 0; j < 8; j += 4) {
            const int c = bcol + tx * 8 + j;
            float4 o;
            o.x = acc[i][j + 0] + bias[c + 0];
            o.y = acc[i][j + 1] + bias[c + 1];
            o.z = acc[i][j + 2] + bias[c + 2];
            o.w = acc[i][j + 3] + bias[c + 3];
            *(float4*)(Cmat + (size_t)r * N + c) = o;
        }
    }
}

// ---------------------------------------------------------------------------
// RoPE + split qkv -> q,k,v in [B*H, T, D] layout. One thread per (b,t,h,pair).
// ---------------------------------------------------------------------------
__global__ void rope_split(const float* __restrict__ qkv,
                           float* __restrict__ Q, float* __restrict__ K2,
                           float* __restrict__ V2)
{
    const int total = Bsz * Tlen * Hn * (Dh / 2);
    int idx = blockIdx.x * blockDim.x + threadIdx.x;
    if (idx >= total) return;

    const int i  = idx & 31;                 // pair index 0..31
    const int h  = (idx >> 5) % Hn;
    const int bt = idx / (32 * Hn);          // b*T + t
    const int t  = bt & (Tlen - 1);

    const float* row = qkv + (size_t)bt * C3;
    const int coff = h * Dh + 2 * i;
    float2 q2 = *(const float2*)(row + coff);
    float2 k2 = *(const float2*)(row + Cdim + coff);
    float2 v2 = *(const float2*)(row + 2 * Cdim + coff);

    // inv_freq = 10000^(-2i/64) = exp(-i * ln(10000)/32)
    const float inv_freq = expf(-(float)i * (9.210340371976184f / 32.0f));
    const float ang = (float)t * inv_freq;
    float s, c;
    sincosf(ang, &s, &c);

    float2 qo, ko;
    qo.x = q2.x * c - q2.y * s;
    qo.y = q2.y * c + q2.x * s;
    ko.x = k2.x * c - k2.y * s;
    ko.y = k2.y * c + k2.x * s;

    const int bh = (bt >> 10) * Hn + h;      // b*H + h
    const size_t o = ((size_t)bh * Tlen + t) * Dh + 2 * i;
    *(float2*)(Q  + o) = qo;
    *(float2*)(K2 + o) = ko;
    *(float2*)(V2 + o) = v2;
}

// ---------------------------------------------------------------------------
// Causal flash attention, fp32. Block = 128 query rows of one (b,h).
// Each thread owns one query row: q[64], acc[64] in registers.
// K/V streamed through smem in 64-key tiles; online softmax in 16-key chunks.
// Output written directly into [B*T, C] layout for the proj GEMM.
// ---------------------------------------------------------------------------
__global__ __launch_bounds__(128) void flash_attn(
    const float* __restrict__ Qg, const float* __restrict__ Kg,
    const float* __restrict__ Vg, float* __restrict__ Yg)
{
    __shared__ float Ks[64][64];
    __shared__ float Vs[64][64];

    const int bh  = blockIdx.y;              // 0..95
    const int qt  = blockIdx.x;              // 0..7  (128-row q tiles)
    const int tid = threadIdx.x;
    const int t   = qt * 128 + tid;

    float q[64], acc[64];
    const float* qptr = Qg + ((size_t)bh * Tlen + t) * Dh;
    #pragma unroll
    for (int d = 0; d < 64; d += 4) {
        float4 v4 = *(const float4*)(qptr + d);
        q[d] = v4.x; q[d + 1] = v4.y; q[d + 2] = v4.z; q[d + 3] = v4.w;
    }
    #pragma unroll
    for (int d = 0; d < 64; ++d) acc[d] = 0.f;

    float m = -INFINITY, l = 0.f;

    const int nkt = 2 * qt + 2;              // 64-key tiles covering causal span
    for (int kt = 0; kt < nkt; ++kt) {
        const int kbase = kt * 64;
        const float* kptr = Kg + ((size_t)bh * Tlen + kbase) * Dh;
        const float* vptr = Vg + ((size_t)bh * Tlen + kbase) * Dh;
        #pragma unroll
        for (int it = 0; it < 8; ++it) {
            const int slot = it * 128 + tid;     // 1024 float4 slots
            const int r  = slot >> 4;
            const int cc = (slot & 15) * 4;
            *(float4*)&Ks[r][cc] = *(const float4*)(kptr + r * 64 + cc);
            *(float4*)&Vs[r][cc] = *(const float4*)(vptr + r * 64 + cc);
        }
        __syncthreads();

        int jmax = t - kbase + 1;
        if (jmax > 64) jmax = 64;
        for (int c0 = 0; c0 < jmax; c0 += 16) {
            float sreg[16];
            float mloc = -INFINITY;
            #pragma unroll
            for (int jj = 0; jj < 16; ++jj) {
                const int j = c0 + jj;
                float sv = 0.f;
                #pragma unroll
                for (int d = 0; d < 64; ++d) sv = fmaf(q[d], Ks[j][d], sv);
                sv *= 0.125f;                      // 1/sqrt(64)
                if (j >= jmax) sv = -INFINITY;     // causal mask
                sreg[jj] = sv;
                mloc = fmaxf(mloc, sv);
            }
            const float mnew  = fmaxf(m, mloc);
            const float alpha = __expf(m - mnew);  // m=-inf -> 0 first time
            l *= alpha;
            #pragma unroll
            for (int d = 0; d < 64; ++d) acc[d] *= alpha;
            #pragma unroll
            for (int jj = 0; jj < 16; ++jj) {
                const float p = __expf(sreg[jj] - mnew);  // -inf -> 0
                l += p;
                #pragma unroll
                for (int d = 0; d < 64; ++d)
                    acc[d] = fmaf(p, Vs[c0 + jj][d], acc[d]);
            }
            m = mnew;
        }
        __syncthreads();
    }

    const int b = bh / Hn, h = bh % Hn;
    const float inv = 1.0f / l;
    float* yp = Yg + ((size_t)(b * Tlen + t)) * Cdim + h * Dh;
    #pragma unroll
    for (int d = 0; d < 64; d += 4) {
        float4 o;
        o.x = acc[d] * inv; o.y = acc[d + 1] * inv;
        o.z = acc[d + 2] * inv; o.w = acc[d + 3] * inv;
        *(float4*)(yp + d) = o;
    }
}

// ---------------------------------------------------------------------------
// Launcher
// ---------------------------------------------------------------------------
extern "C" void kernel_launch(void* const* d_in, const int* in_sizes, int n_in,
                              void* d_out, int out_size)
{
    const float* x      = (const float*)d_in[0];
    const float* W_attn = (const float*)d_in[1];
    const float* b_attn = (const float*)d_in[2];
    const float* W_proj = (const float*)d_in[3];
    const float* b_proj = (const float*)d_in[4];
    float* out = (float*)d_out;

    void *p_qkv, *p_q, *p_k, *p_v, *p_y;
    cudaGetSymbolAddress(&p_qkv, g_qkv);
    cudaGetSymbolAddress(&p_q,   g_q);
    cudaGetSymbolAddress(&p_k,   g_k);
    cudaGetSymbolAddress(&p_v,   g_v);
    cudaGetSymbolAddress(&p_y,   g_y);
    float* qkv = (float*)p_qkv;
    float* q   = (float*)p_q;
    float* k   = (float*)p_k;
    float* v   = (float*)p_v;
    float* y   = (float*)p_y;

    // 1) qkv = x @ W_attn + b_attn   (8192 x 2304 x 768)
    {
        dim3 grid(C3 / 128, BT / 128);
        sgemm_bias<<<grid, 256>>>(x, W_attn, b_attn, qkv, BT, C3, Cdim);
    }

    // 2) RoPE + split into [B*H, T, D]
    {
        const int total = Bsz * Tlen * Hn * (Dh / 2);
        rope_split<<<(total + 255) / 256, 256>>>(qkv, q, k, v);
    }

    // 3) causal flash attention -> y in [B*T, C]
    {
        dim3 grid(Tlen / 128, BH);
        flash_attn<<<grid, 128>>>(q, k, v, y);
    }

    // 4) out = y @ W_proj + b_proj   (8192 x 768 x 768)
    {
        dim3 grid(Cdim / 128, BT / 128);
        sgemm_bias<<<grid, 256>>>(y, W_proj, b_proj, out, BT, Cdim, Cdim);
    }
}

// round 3
// speedup vs baseline: 1.4010x; 1.4010x over previous
#include <cuda_runtime.h>
#include <cuda_bf16.h>
#include <math.h>
#include <stdint.h>

#define Bsz   8
#define Tlen  1024
#define Cdim  768
#define Hn    12
#define Dh    64
#define BT    (Bsz * Tlen)     // 8192
#define C3    (3 * Cdim)       // 2304
#define BH    (Bsz * Hn)       // 96
#define Kdim  768

// ---------------- scratch (device globals; no cudaMalloc allowed) ----------
__device__ float g_qkv[BT * C3];
__device__ float g_q[BH * Tlen * Dh];
__device__ float g_k[BH * Tlen * Dh];
__device__ float g_v[BH * Tlen * Dh];
__device__ float g_y[BT * Cdim];

__device__ __nv_bfloat16 g_xh[BT * Cdim];   // bf16 hi/mid splits of x
__device__ __nv_bfloat16 g_xm[BT * Cdim];
__device__ __nv_bfloat16 g_yh[BT * Cdim];   // splits of attention output
__device__ __nv_bfloat16 g_ym[BT * Cdim];
__device__ __nv_bfloat16 g_wah[C3 * Cdim];  // W_attn^T splits [2304][768]
__device__ __nv_bfloat16 g_wam[C3 * Cdim];
__device__ __nv_bfloat16 g_wph[Cdim * Cdim];
__device__ __nv_bfloat16 g_wpm[Cdim * Cdim];

// ---------------- PTX helpers ----------------------------------------------
__device__ __forceinline__ uint32_t smem_u32(const void* p) {
    uint32_t a;
    asm("{ .reg .u64 t; cvta.to.shared.u64 t, %1; cvt.u32.u64 %0, t; }"
        : "=r"(a) : "l"(p));
    return a;
}
__device__ __forceinline__ void cpasync16(uint32_t dst, const void* src) {
    asm volatile("cp.async.cg.shared.global [%0], [%1], 16;\n" :: "r"(dst), "l"(src));
}
__device__ __forceinline__ void cp_commit() {
    asm volatile("cp.async.commit_group;\n" ::: "memory");
}
__device__ __forceinline__ void cp_wait1() {
    asm volatile("cp.async.wait_group 1;\n" ::: "memory");
}
__device__ __forceinline__ void cp_wait0() {
    asm volatile("cp.async.wait_group 0;\n" ::: "memory");
}
__device__ __forceinline__ void ldsm4(uint32_t (&r)[4], uint32_t addr) {
    asm volatile("ldmatrix.sync.aligned.m8n8.x4.shared.b16 {%0,%1,%2,%3}, [%4];"
        : "=r"(r[0]), "=r"(r[1]), "=r"(r[2]), "=r"(r[3]) : "r"(addr));
}
__device__ __forceinline__ void mma_bf16(float (&c)[4], const uint32_t (&a)[4],
                                         uint32_t b0, uint32_t b1) {
    asm volatile(
        "mma.sync.aligned.m16n8k16.row.col.f32.bf16.bf16.f32 "
        "{%0,%1,%2,%3}, {%4,%5,%6,%7}, {%8,%9}, {%0,%1,%2,%3};"
        : "+f"(c[0]), "+f"(c[1]), "+f"(c[2]), "+f"(c[3])
        : "r"(a[0]), "r"(a[1]), "r"(a[2]), "r"(a[3]), "r"(b0), "r"(b1));
}

// ---------------------------------------------------------------------------
// bf16x3 GEMM: C[M=8192, Nt] = A[8192,768] @ Bt[Nt,768]^T + bias
// A,B given as bf16 hi/mid splits. 3 accumulation passes:
//   (Ah,Bh), (Am,Bh), (Ah,Bm)  -> error O(2^-18), well under 1e-3.
// CTA 128x128, 8 warps (2x4), warp tile 64x32, K-tile 32, double-buffered.
// ---------------------------------------------------------------------------
#define GM_NKT  (Kdim / 32)        // 24
#define GM_NIT  (3 * GM_NKT)       // 72
#define ASTRIDE 40                 // bf16 elems per smem row (80 bytes)

__global__ __launch_bounds__(256, 2) void gemm_bf16x3(
    const __nv_bfloat16* __restrict__ A1, const __nv_bfloat16* __restrict__ A2,
    const __nv_bfloat16* __restrict__ B1, const __nv_bfloat16* __restrict__ B2,
    const float* __restrict__ bias, float* __restrict__ C, int Nt)
{
    __shared__ __align__(16) __nv_bfloat16 As[2][128 * ASTRIDE];
    __shared__ __align__(16) __nv_bfloat16 Bs[2][128 * ASTRIDE];

    const int tid  = threadIdx.x;
    const int wid  = tid >> 5;
    const int lane = tid & 31;
    const int wm   = wid >> 2;       // 0..1
    const int wn   = wid & 3;        // 0..3
    const int brow = blockIdx.y * 128;
    const int bcol = blockIdx.x * 128;

    const uint32_t sA = smem_u32(&As[0][0]);
    const uint32_t sB = smem_u32(&Bs[0][0]);
    const uint32_t STG = 128 * ASTRIDE * 2;   // bytes per stage (10240)

    // ldmatrix lane offsets (bytes)
    const uint32_t a_off =
        (uint32_t)(((wm * 64 + (lane & 15)) * ASTRIDE + (lane >> 4) * 8) * 2);
    const uint32_t b_off =
        (uint32_t)(((wn * 32 + (lane & 7) + ((lane >> 4) & 1) * 8) * ASTRIDE
                    + ((lane >> 3) & 1) * 8) * 2);

    float c[4][4][4];
    #pragma unroll
    for (int i = 0; i < 4; ++i)
        #pragma unroll
        for (int j = 0; j < 4; ++j)
            #pragma unroll
            for (int r = 0; r < 4; ++r) c[i][j][r] = 0.f;

    // stage loader: iteration i -> (pass, k0)
    auto load_stage = [&](int s, int i) {
        const int p  = i / GM_NKT;
        const int k0 = (i % GM_NKT) * 32;
        const __nv_bfloat16* Ap = (p == 1) ? A2 : A1;
        const __nv_bfloat16* Bp = (p == 2) ? B2 : B1;
        #pragma unroll
        for (int j = 0; j < 2; ++j) {
            const int idx = j * 256 + tid;        // 0..511
            const int row = idx >> 2, c4 = idx & 3;
            cpasync16(sA + s * STG + row * (ASTRIDE * 2) + c4 * 16,
                      Ap + (size_t)(brow + row) * Kdim + k0 + c4 * 8);
            cpasync16(sB + s * STG + row * (ASTRIDE * 2) + c4 * 16,
                      Bp + (size_t)(bcol + row) * Kdim + k0 + c4 * 8);
        }
        cp_commit();
    };

    load_stage(0, 0);
    load_stage(1, 1);

    for (int i = 0; i < GM_NIT; ++i) {
        const int s = i & 1;
        if (i + 2 < GM_NIT) cp_wait1(); else cp_wait0();
        __syncthreads();

        const uint32_t aB = sA + s * STG + a_off;
        const uint32_t bB = sB + s * STG + b_off;
        #pragma unroll
        for (int ks = 0; ks < 2; ++ks) {
            uint32_t a[4][4];
            #pragma unroll
            for (int mt = 0; mt < 4; ++mt)
                ldsm4(a[mt], aB + mt * (16 * ASTRIDE * 2) + ks * 32);
            uint32_t b[2][4];
            #pragma unroll
            for (int nt2 = 0; nt2 < 2; ++nt2)
                ldsm4(b[nt2], bB + nt2 * (16 * ASTRIDE * 2) + ks * 32);
            #pragma unroll
            for (int mt = 0; mt < 4; ++mt)
                #pragma unroll
                for (int nt = 0; nt < 4; ++nt)
                    mma_bf16(c[mt][nt], a[mt],
                             b[nt >> 1][(nt & 1) * 2], b[nt >> 1][(nt & 1) * 2 + 1]);
        }
        __syncthreads();

        if (i + 2 < GM_NIT) load_stage(s, i + 2);
    }

    // epilogue: add bias, store fp32
    #pragma unroll
    for (int mt = 0; mt < 4; ++mt) {
        const int gr = brow + wm * 64 + mt * 16 + (lane >> 2);
        #pragma unroll
        for (int nt = 0; nt < 4; ++nt) {
            const int gc = bcol + wn * 32 + nt * 8 + (lane & 3) * 2;
            const float bx = bias[gc], by = bias[gc + 1];
            float2 o0, o1;
            o0.x = c[mt][nt][0] + bx; o0.y = c[mt][nt][1] + by;
            o1.x = c[mt][nt][2] + bx; o1.y = c[mt][nt][3] + by;
            *(float2*)(C + (size_t)gr * Nt + gc)       = o0;
            *(float2*)(C + (size_t)(gr + 8) * Nt + gc) = o1;
        }
    }
}

// ---------------------------------------------------------------------------
// fp32 -> bf16 hi/mid split (elementwise)
// ---------------------------------------------------------------------------
__global__ void split_bf16(const float4* __restrict__ src,
                           __nv_bfloat162* __restrict__ hi,
                           __nv_bfloat162* __restrict__ mid, int n4)
{
    int i = blockIdx.x * blockDim.x + threadIdx.x;
    if (i >= n4) return;
    float4 v = src[i];
    __nv_bfloat16 hx = __float2bfloat16(v.x), hy = __float2bfloat16(v.y);
    __nv_bfloat16 hz = __float2bfloat16(v.z), hw = __float2bfloat16(v.w);
    __nv_bfloat16 mx = __float2bfloat16(v.x - __bfloat162float(hx));
    __nv_bfloat16 my = __float2bfloat16(v.y - __bfloat162float(hy));
    __nv_bfloat16 mz = __float2bfloat16(v.z - __bfloat162float(hz));
    __nv_bfloat16 mw = __float2bfloat16(v.w - __bfloat162float(hw));
    hi[i * 2]      = __nv_bfloat162(hx, hy);
    hi[i * 2 + 1]  = __nv_bfloat162(hz, hw);
    mid[i * 2]     = __nv_bfloat162(mx, my);
    mid[i * 2 + 1] = __nv_bfloat162(mz, mw);
}

// ---------------------------------------------------------------------------
// transpose + bf16 split: W[K][N] -> Th/Tm[N][K] bf16
// ---------------------------------------------------------------------------
__global__ void trans_split_bf16(const float* __restrict__ W,
                                 __nv_bfloat16* __restrict__ Th,
                                 __nv_bfloat16* __restrict__ Tm, int K, int N)
{
    __shared__ float tile[32][33];
    const int kb = blockIdx.y * 32, nb = blockIdx.x * 32;
    const int tx = threadIdx.x, ty = threadIdx.y;
    #pragma unroll
    for (int r = ty; r < 32; r += 8)
        tile[r][tx] = W[(size_t)(kb + r) * N + nb + tx];
    __syncthreads();
    #pragma unroll
    for (int i = ty; i < 32; i += 8) {
        float v = tile[tx][i];
        __nv_bfloat16 h = __float2bfloat16(v);
        __nv_bfloat16 m = __float2bfloat16(v - __bfloat162float(h));
        Th[(size_t)(nb + i) * K + kb + tx] = h;
        Tm[(size_t)(nb + i) * K + kb + tx] = m;
    }
}

// ---------------------------------------------------------------------------
// RoPE + split qkv -> q,k,v in [B*H, T, D]
// ---------------------------------------------------------------------------
__global__ void rope_split(const float* __restrict__ qkv,
                           float* __restrict__ Q, float* __restrict__ K2,
                           float* __restrict__ V2)
{
    const int total = Bsz * Tlen * Hn * (Dh / 2);
    int idx = blockIdx.x * blockDim.x + threadIdx.x;
    if (idx >= total) return;

    const int i  = idx & 31;
    const int h  = (idx >> 5) % Hn;
    const int bt = idx / (32 * Hn);
    const int t  = bt & (Tlen - 1);

    const float* row = qkv + (size_t)bt * C3;
    const int coff = h * Dh + 2 * i;
    float2 q2 = *(const float2*)(row + coff);
    float2 k2 = *(const float2*)(row + Cdim + coff);
    float2 v2 = *(const float2*)(row + 2 * Cdim + coff);

    const float inv_freq = expf(-(float)i * (9.210340371976184f / 32.0f));
    const float ang = (float)t * inv_freq;
    float s, c;
    sincosf(ang, &s, &c);

    float2 qo, ko;
    qo.x = q2.x * c - q2.y * s;
    qo.y = q2.y * c + q2.x * s;
    ko.x = k2.x * c - k2.y * s;
    ko.y = k2.y * c + k2.x * s;

    const int bh = (bt >> 10) * Hn + h;
    const size_t o = ((size_t)bh * Tlen + t) * Dh + 2 * i;
    *(float2*)(Q  + o) = qo;
    *(float2*)(K2 + o) = ko;
    *(float2*)(V2 + o) = v2;
}

// ---------------------------------------------------------------------------
// Causal flash attention, fp32 (unchanged)
// ---------------------------------------------------------------------------
__global__ __launch_bounds__(128) void flash_attn(
    const float* __restrict__ Qg, const float* __restrict__ Kg,
    const float* __restrict__ Vg, float* __restrict__ Yg)
{
    __shared__ float Ks[64][64];
    __shared__ float Vs[64][64];

    const int bh  = blockIdx.y;
    const int qt  = blockIdx.x;
    const int tid = threadIdx.x;
    const int t   = qt * 128 + tid;

    float q[64], acc[64];
    const float* qptr = Qg + ((size_t)bh * Tlen + t) * Dh;
    #pragma unroll
    for (int d = 0; d < 64; d += 4) {
        float4 v4 = *(const float4*)(qptr + d);
        q[d] = v4.x; q[d + 1] = v4.y; q[d + 2] = v4.z; q[d + 3] = v4.w;
    }
    #pragma unroll
    for (int d = 0; d < 64; ++d) acc[d] = 0.f;

    float m = -INFINITY, l = 0.f;

    const int nkt = 2 * qt + 2;
    for (int kt = 0; kt < nkt; ++kt) {
        const int kbase = kt * 64;
        const float* kptr = Kg + ((size_t)bh * Tlen + kbase) * Dh;
        const float* vptr = Vg + ((size_t)bh * Tlen + kbase) * Dh;
        #pragma unroll
        for (int it = 0; it < 8; ++it) {
            const int slot = it * 128 + tid;
            const int r  = slot >> 4;
            const int cc = (slot & 15) * 4;
            *(float4*)&Ks[r][cc] = *(const float4*)(kptr + r * 64 + cc);
            *(float4*)&Vs[r][cc] = *(const float4*)(vptr + r * 64 + cc);
        }
        __syncthreads();

        int jmax = t - kbase + 1;
        if (jmax > 64) jmax = 64;
        for (int c0 = 0; c0 < jmax; c0 += 16) {
            float sreg[16];
            float mloc = -INFINITY;
            #pragma unroll
            for (int jj = 0; jj < 16; ++jj) {
                const int j = c0 + jj;
                float sv = 0.f;
                #pragma unroll
                for (int d = 0; d < 64; ++d) sv = fmaf(q[d], Ks[j][d], sv);
                sv *= 0.125f;
                if (j >= jmax) sv = -INFINITY;
                sreg[jj] = sv;
                mloc = fmaxf(mloc, sv);
            }
            const float mnew  = fmaxf(m, mloc);
            const float alpha = __expf(m - mnew);
            l *= alpha;
            #pragma unroll
            for (int d = 0; d < 64; ++d) acc[d] *= alpha;
            #pragma unroll
            for (int jj = 0; jj < 16; ++jj) {
                const float p = __expf(sreg[jj] - mnew);
                l += p;
                #pragma unroll
                for (int d = 0; d < 64; ++d)
                    acc[d] = fmaf(p, Vs[c0 + jj][d], acc[d]);
            }
            m = mnew;
        }
        __syncthreads();
    }

    const int b = bh / Hn, h = bh % Hn;
    const float inv = 1.0f / l;
    float* yp = Yg + ((size_t)(b * Tlen + t)) * Cdim + h * Dh;
    #pragma unroll
    for (int d = 0; d < 64; d += 4) {
        float4 o;
        o.x = acc[d] * inv; o.y = acc[d + 1] * inv;
        o.z = acc[d + 2] * inv; o.w = acc[d + 3] * inv;
        *(float4*)(yp + d) = o;
    }
}

// ---------------------------------------------------------------------------
// Launcher
// ---------------------------------------------------------------------------
extern "C" void kernel_launch(void* const* d_in, const int* in_sizes, int n_in,
                              void* d_out, int out_size)
{
    const float* x      = (const float*)d_in[0];
    const float* W_attn = (const float*)d_in[1];
    const float* b_attn = (const float*)d_in[2];
    const float* W_proj = (const float*)d_in[3];
    const float* b_proj = (const float*)d_in[4];
    float* out = (float*)d_out;

    void* p;
    float *qkv, *q, *k, *v, *y;
    __nv_bfloat16 *xh, *xm, *yh, *ym, *wah, *wam, *wph, *wpm;
    cudaGetSymbolAddress(&p, g_qkv); qkv = (float*)p;
    cudaGetSymbolAddress(&p, g_q);   q   = (float*)p;
    cudaGetSymbolAddress(&p, g_k);   k   = (float*)p;
    cudaGetSymbolAddress(&p, g_v);   v   = (float*)p;
    cudaGetSymbolAddress(&p, g_y);   y   = (float*)p;
    cudaGetSymbolAddress(&p, g_xh);  xh  = (__nv_bfloat16*)p;
    cudaGetSymbolAddress(&p, g_xm);  xm  = (__nv_bfloat16*)p;
    cudaGetSymbolAddress(&p, g_yh);  yh  = (__nv_bfloat16*)p;
    cudaGetSymbolAddress(&p, g_ym);  ym  = (__nv_bfloat16*)p;
    cudaGetSymbolAddress(&p, g_wah); wah = (__nv_bfloat16*)p;
    cudaGetSymbolAddress(&p, g_wam); wam = (__nv_bfloat16*)p;
    cudaGetSymbolAddress(&p, g_wph); wph = (__nv_bfloat16*)p;
    cudaGetSymbolAddress(&p, g_wpm); wpm = (__nv_bfloat16*)p;

    // prep: splits + transposes
    {
        const int n4 = BT * Cdim / 4;
        split_bf16<<<(n4 + 255) / 256, 256>>>((const float4*)x,
            (__nv_bfloat162*)xh, (__nv_bfloat162*)xm, n4);
        dim3 g1(C3 / 32, Kdim / 32);
        trans_split_bf16<<<g1, dim3(32, 8)>>>(W_attn, wah, wam, Kdim, C3);
        dim3 g2(Cdim / 32, Kdim / 32);
        trans_split_bf16<<<g2, dim3(32, 8)>>>(W_proj, wph, wpm, Kdim, Cdim);
    }

    // 1) qkv = x @ W_attn + b_attn  (bf16x3 tensor-core)
    {
        dim3 grid(C3 / 128, BT / 128);    // (18, 64)
        gemm_bf16x3<<<grid, 256>>>(xh, xm, wah, wam, b_attn, qkv, C3);
    }

    // 2) RoPE + split into [B*H, T, D]
    {
        const int total = Bsz * Tlen * Hn * (Dh / 2);
        rope_split<<<(total + 255) / 256, 256>>>(qkv, q, k, v);
    }

    // 3) causal flash attention
    {
        dim3 grid(Tlen / 128, BH);
        flash_attn<<<grid, 128>>>(q, k, v, y);
    }

    // 4) out = y @ W_proj + b_proj  (bf16x3 tensor-core)
    {
        const int n4 = BT * Cdim / 4;
        split_bf16<<<(n4 + 255) / 256, 256>>>((const float4*)y,
            (__nv_bfloat162*)yh, (__nv_bfloat162*)ym, n4);
        dim3 grid(Cdim / 128, BT / 128);  // (6, 64)
        gemm_bf16x3<<<grid, 256>>>(yh, ym, wph, wpm, b_proj, out, Cdim);
    }
}

// round 4
// speedup vs baseline: 3.1920x; 2.2784x over previous
#include <cuda_runtime.h>
#include <cuda_bf16.h>
#include <math.h>
#include <stdint.h>

#define Bsz   8
#define Tlen  1024
#define Cdim  768
#define Hn    12
#define Dh    64
#define BT    (Bsz * Tlen)     // 8192
#define C3    (3 * Cdim)       // 2304
#define BH    (Bsz * Hn)       // 96
#define Kdim  768

// ---------------- scratch (device globals; no cudaMalloc allowed) ----------
__device__ float g_qkv[BT * C3];

__device__ __nv_bfloat16 g_xh[BT * Cdim];
__device__ __nv_bfloat16 g_xm[BT * Cdim];
__device__ __nv_bfloat16 g_wah[C3 * Cdim];
__device__ __nv_bfloat16 g_wam[C3 * Cdim];
__device__ __nv_bfloat16 g_wph[Cdim * Cdim];
__device__ __nv_bfloat16 g_wpm[Cdim * Cdim];

// RoPE'd q/k/v as bf16 hi/mid splits, [B*H, T, D]
__device__ __nv_bfloat16 g_qh[BH * Tlen * Dh];
__device__ __nv_bfloat16 g_qm[BH * Tlen * Dh];
__device__ __nv_bfloat16 g_kh[BH * Tlen * Dh];
__device__ __nv_bfloat16 g_km[BH * Tlen * Dh];
__device__ __nv_bfloat16 g_vh[BH * Tlen * Dh];
__device__ __nv_bfloat16 g_vm[BH * Tlen * Dh];

// attention output splits, [B*T, C]
__device__ __nv_bfloat16 g_yh[BT * Cdim];
__device__ __nv_bfloat16 g_ym[BT * Cdim];

// ---------------- PTX helpers ----------------------------------------------
__device__ __forceinline__ uint32_t smem_u32(const void* p) {
    uint32_t a;
    asm("{ .reg .u64 t; cvta.to.shared.u64 t, %1; cvt.u32.u64 %0, t; }"
        : "=r"(a) : "l"(p));
    return a;
}
__device__ __forceinline__ void cpasync16(uint32_t dst, const void* src) {
    asm volatile("cp.async.cg.shared.global [%0], [%1], 16;\n" :: "r"(dst), "l"(src));
}
__device__ __forceinline__ void cp_commit() {
    asm volatile("cp.async.commit_group;\n" ::: "memory");
}
__device__ __forceinline__ void cp_wait1() {
    asm volatile("cp.async.wait_group 1;\n" ::: "memory");
}
__device__ __forceinline__ void cp_wait0() {
    asm volatile("cp.async.wait_group 0;\n" ::: "memory");
}
__device__ __forceinline__ void ldsm4(uint32_t (&r)[4], uint32_t addr) {
    asm volatile("ldmatrix.sync.aligned.m8n8.x4.shared.b16 {%0,%1,%2,%3}, [%4];"
        : "=r"(r[0]), "=r"(r[1]), "=r"(r[2]), "=r"(r[3]) : "r"(addr));
}
__device__ __forceinline__ void ldsm4t(uint32_t (&r)[4], uint32_t addr) {
    asm volatile("ldmatrix.sync.aligned.m8n8.x4.trans.shared.b16 {%0,%1,%2,%3}, [%4];"
        : "=r"(r[0]), "=r"(r[1]), "=r"(r[2]), "=r"(r[3]) : "r"(addr));
}
__device__ __forceinline__ void mma_bf16(float (&c)[4], const uint32_t (&a)[4],
                                         uint32_t b0, uint32_t b1) {
    asm volatile(
        "mma.sync.aligned.m16n8k16.row.col.f32.bf16.bf16.f32 "
        "{%0,%1,%2,%3}, {%4,%5,%6,%7}, {%8,%9}, {%0,%1,%2,%3};"
        : "+f"(c[0]), "+f"(c[1]), "+f"(c[2]), "+f"(c[3])
        : "r"(a[0]), "r"(a[1]), "r"(a[2]), "r"(a[3]), "r"(b0), "r"(b1));
}
__device__ __forceinline__ float ex2(float x) {
    float y;
    asm("ex2.approx.f32 %0, %1;" : "=f"(y) : "f"(x));
    return y;
}
__device__ __forceinline__ void pack_hm(float p0, float p1, uint32_t& hi, uint32_t& mid) {
    __nv_bfloat162 h = __floats2bfloat162_rn(p0, p1);
    float r0 = p0 - __bfloat162float(h.x);
    float r1 = p1 - __bfloat162float(h.y);
    __nv_bfloat162 m = __floats2bfloat162_rn(r0, r1);
    hi  = *(uint32_t*)&h;
    mid = *(uint32_t*)&m;
}

// ---------------------------------------------------------------------------
// bf16x3 GEMM (unchanged from R3): C = A @ Bt^T + bias
// ---------------------------------------------------------------------------
#define GM_NKT  (Kdim / 32)
#define GM_NIT  (3 * GM_NKT)
#define ASTRIDE 40

__global__ __launch_bounds__(256, 2) void gemm_bf16x3(
    const __nv_bfloat16* __restrict__ A1, const __nv_bfloat16* __restrict__ A2,
    const __nv_bfloat16* __restrict__ B1, const __nv_bfloat16* __restrict__ B2,
    const float* __restrict__ bias, float* __restrict__ C, int Nt)
{
    __shared__ __align__(16) __nv_bfloat16 As[2][128 * ASTRIDE];
    __shared__ __align__(16) __nv_bfloat16 Bs[2][128 * ASTRIDE];

    const int tid  = threadIdx.x;
    const int wid  = tid >> 5;
    const int lane = tid & 31;
    const int wm   = wid >> 2;
    const int wn   = wid & 3;
    const int brow = blockIdx.y * 128;
    const int bcol = blockIdx.x * 128;

    const uint32_t sA = smem_u32(&As[0][0]);
    const uint32_t sB = smem_u32(&Bs[0][0]);
    const uint32_t STG = 128 * ASTRIDE * 2;

    const uint32_t a_off =
        (uint32_t)(((wm * 64 + (lane & 15)) * ASTRIDE + (lane >> 4) * 8) * 2);
    const uint32_t b_off =
        (uint32_t)(((wn * 32 + (lane & 7) + ((lane >> 4) & 1) * 8) * ASTRIDE
                    + ((lane >> 3) & 1) * 8) * 2);

    float c[4][4][4];
    #pragma unroll
    for (int i = 0; i < 4; ++i)
        #pragma unroll
        for (int j = 0; j < 4; ++j)
            #pragma unroll
            for (int r = 0; r < 4; ++r) c[i][j][r] = 0.f;

    auto load_stage = [&](int s, int i) {
        const int p  = i / GM_NKT;
        const int k0 = (i % GM_NKT) * 32;
        const __nv_bfloat16* Ap = (p == 1) ? A2 : A1;
        const __nv_bfloat16* Bp = (p == 2) ? B2 : B1;
        #pragma unroll
        for (int j = 0; j < 2; ++j) {
            const int idx = j * 256 + tid;
            const int row = idx >> 2, c4 = idx & 3;
            cpasync16(sA + s * STG + row * (ASTRIDE * 2) + c4 * 16,
                      Ap + (size_t)(brow + row) * Kdim + k0 + c4 * 8);
            cpasync16(sB + s * STG + row * (ASTRIDE * 2) + c4 * 16,
                      Bp + (size_t)(bcol + row) * Kdim + k0 + c4 * 8);
        }
        cp_commit();
    };

    load_stage(0, 0);
    load_stage(1, 1);

    for (int i = 0; i < GM_NIT; ++i) {
        const int s = i & 1;
        if (i + 2 < GM_NIT) cp_wait1(); else cp_wait0();
        __syncthreads();

        const uint32_t aB = sA + s * STG + a_off;
        const uint32_t bB = sB + s * STG + b_off;
        #pragma unroll
        for (int ks = 0; ks < 2; ++ks) {
            uint32_t a[4][4];
            #pragma unroll
            for (int mt = 0; mt < 4; ++mt)
                ldsm4(a[mt], aB + mt * (16 * ASTRIDE * 2) + ks * 32);
            uint32_t b[2][4];
            #pragma unroll
            for (int nt2 = 0; nt2 < 2; ++nt2)
                ldsm4(b[nt2], bB + nt2 * (16 * ASTRIDE * 2) + ks * 32);
            #pragma unroll
            for (int mt = 0; mt < 4; ++mt)
                #pragma unroll
                for (int nt = 0; nt < 4; ++nt)
                    mma_bf16(c[mt][nt], a[mt],
                             b[nt >> 1][(nt & 1) * 2], b[nt >> 1][(nt & 1) * 2 + 1]);
        }
        __syncthreads();

        if (i + 2 < GM_NIT) load_stage(s, i + 2);
    }

    #pragma unroll
    for (int mt = 0; mt < 4; ++mt) {
        const int gr = brow + wm * 64 + mt * 16 + (lane >> 2);
        #pragma unroll
        for (int nt = 0; nt < 4; ++nt) {
            const int gc = bcol + wn * 32 + nt * 8 + (lane & 3) * 2;
            const float bx = bias[gc], by = bias[gc + 1];
            float2 o0, o1;
            o0.x = c[mt][nt][0] + bx; o0.y = c[mt][nt][1] + by;
            o1.x = c[mt][nt][2] + bx; o1.y = c[mt][nt][3] + by;
            *(float2*)(C + (size_t)gr * Nt + gc)       = o0;
            *(float2*)(C + (size_t)(gr + 8) * Nt + gc) = o1;
        }
    }
}

// ---------------------------------------------------------------------------
// fp32 -> bf16 hi/mid split (x only now)
// ---------------------------------------------------------------------------
__global__ void split_bf16(const float4* __restrict__ src,
                           __nv_bfloat162* __restrict__ hi,
                           __nv_bfloat162* __restrict__ mid, int n4)
{
    int i = blockIdx.x * blockDim.x + threadIdx.x;
    if (i >= n4) return;
    float4 v = src[i];
    uint32_t h0, m0, h1, m1;
    pack_hm(v.x, v.y, h0, m0);
    pack_hm(v.z, v.w, h1, m1);
    hi[i * 2]      = *(__nv_bfloat162*)&h0;
    hi[i * 2 + 1]  = *(__nv_bfloat162*)&h1;
    mid[i * 2]     = *(__nv_bfloat162*)&m0;
    mid[i * 2 + 1] = *(__nv_bfloat162*)&m1;
}

// ---------------------------------------------------------------------------
// transpose + bf16 split: W[K][N] -> Th/Tm[N][K]
// ---------------------------------------------------------------------------
__global__ void trans_split_bf16(const float* __restrict__ W,
                                 __nv_bfloat16* __restrict__ Th,
                                 __nv_bfloat16* __restrict__ Tm, int K, int N)
{
    __shared__ float tile[32][33];
    const int kb = blockIdx.y * 32, nb = blockIdx.x * 32;
    const int tx = threadIdx.x, ty = threadIdx.y;
    #pragma unroll
    for (int r = ty; r < 32; r += 8)
        tile[r][tx] = W[(size_t)(kb + r) * N + nb + tx];
    __syncthreads();
    #pragma unroll
    for (int i = ty; i < 32; i += 8) {
        float v = tile[tx][i];
        __nv_bfloat16 h = __float2bfloat16(v);
        __nv_bfloat16 m = __float2bfloat16(v - __bfloat162float(h));
        Th[(size_t)(nb + i) * K + kb + tx] = h;
        Tm[(size_t)(nb + i) * K + kb + tx] = m;
    }
}

// ---------------------------------------------------------------------------
// RoPE + split into bf16 hi/mid. q pre-scaled by 0.125*log2(e) so attention
// scores come out in log2 domain (softmax uses ex2 directly).
// ---------------------------------------------------------------------------
#define QSCALE (0.125f * 1.4426950408889634f)

__global__ void rope_split_bf16(const float* __restrict__ qkv,
    __nv_bfloat162* __restrict__ Qh, __nv_bfloat162* __restrict__ Qm,
    __nv_bfloat162* __restrict__ Kh, __nv_bfloat162* __restrict__ Km,
    __nv_bfloat162* __restrict__ Vh, __nv_bfloat162* __restrict__ Vm)
{
    const int total = Bsz * Tlen * Hn * (Dh / 2);
    int idx = blockIdx.x * blockDim.x + threadIdx.x;
    if (idx >= total) return;

    const int i  = idx & 31;
    const int h  = (idx >> 5) % Hn;
    const int bt = idx / (32 * Hn);
    const int t  = bt & (Tlen - 1);

    const float* row = qkv + (size_t)bt * C3;
    const int coff = h * Dh + 2 * i;
    float2 q2 = *(const float2*)(row + coff);
    float2 k2 = *(const float2*)(row + Cdim + coff);
    float2 v2 = *(const float2*)(row + 2 * Cdim + coff);

    const float inv_freq = expf(-(float)i * (9.210340371976184f / 32.0f));
    const float ang = (float)t * inv_freq;
    float s, c;
    sincosf(ang, &s, &c);

    float qx = (q2.x * c - q2.y * s) * QSCALE;
    float qy = (q2.y * c + q2.x * s) * QSCALE;
    float kx = k2.x * c - k2.y * s;
    float ky = k2.y * c + k2.x * s;

    const int bh = (bt >> 10) * Hn + h;
    const size_t o = ((size_t)bh * Tlen + t) * (Dh / 2) + i;

    uint32_t hh, mm;
    pack_hm(qx, qy, hh, mm);
    Qh[o] = *(__nv_bfloat162*)&hh; Qm[o] = *(__nv_bfloat162*)&mm;
    pack_hm(kx, ky, hh, mm);
    Kh[o] = *(__nv_bfloat162*)&hh; Km[o] = *(__nv_bfloat162*)&mm;
    pack_hm(v2.x, v2.y, hh, mm);
    Vh[o] = *(__nv_bfloat162*)&hh; Vm[o] = *(__nv_bfloat162*)&mm;
}

// ---------------------------------------------------------------------------
// Tensor-core causal flash attention (bf16x3 QK and PV, fp32 softmax).
// CTA = 256 threads, 8 warps; warp owns 16 q rows; q-tile 128, key tiles 64.
// Writes output directly as bf16 hi/mid splits into [B*T, C].
// ---------------------------------------------------------------------------
#define FA_STR   72                      // smem row stride (bf16 elems)
#define FA_ROWB  (FA_STR * 2)            // 144 bytes
#define FA_ARRB  (64 * FA_ROWB)          // 9216 bytes per 64x64 tile
#define FA_STGB  (4 * FA_ARRB)           // 36864 bytes per stage
#define FA_SMEM  (2 * FA_STGB)           // 73728 bytes

__global__ __launch_bounds__(256, 1) void flash_mma(
    const __nv_bfloat16* __restrict__ Qh, const __nv_bfloat16* __restrict__ Qm,
    const __nv_bfloat16* __restrict__ Kh, const __nv_bfloat16* __restrict__ Km,
    const __nv_bfloat16* __restrict__ Vh, const __nv_bfloat16* __restrict__ Vm,
    __nv_bfloat16* __restrict__ Yh, __nv_bfloat16* __restrict__ Ym)
{
    extern __shared__ __align__(16) char sm_raw[];
    const uint32_t sb = smem_u32(sm_raw);
    const int tid  = threadIdx.x;
    const int wid  = tid >> 5;
    const int lane = tid & 31;
    const int bh   = blockIdx.y;
    const int qt   = 7 - blockIdx.x;               // heavy tiles first
    const size_t bhoff = (size_t)bh * (Tlen * Dh);

    // ---- Phase 0: Q hi/mid into smem, then ldmatrix to registers ----------
    #pragma unroll
    for (int j = 0; j < 8; ++j) {
        const int idx = j * 256 + tid;             // 0..2047
        const int arr = idx >> 10;                 // 0: qh, 1: qm
        const int rem = idx & 1023;
        const int row = rem >> 3, c8 = rem & 7;
        const __nv_bfloat16* s = arr ? Qm : Qh;
        cpasync16(sb + arr * (128 * FA_ROWB) + row * FA_ROWB + c8 * 16,
                  s + bhoff + ((size_t)(qt * 128 + row)) * Dh + c8 * 8);
    }
    cp_commit(); cp_wait0(); __syncthreads();

    uint32_t qhf[4][4], qmf[4][4];
    {
        const uint32_t base =
            sb + ((wid * 16 + (lane & 15)) * FA_STR + (lane >> 4) * 8) * 2;
        #pragma unroll
        for (int ks = 0; ks < 4; ++ks) {
            ldsm4(qhf[ks], base + ks * 32);
            ldsm4(qmf[ks], base + ks * 32 + 128 * FA_ROWB);
        }
    }
    __syncthreads();

    // ---- state -------------------------------------------------------------
    float O[8][4];
    #pragma unroll
    for (int n = 0; n < 8; ++n)
        #pragma unroll
        for (int r = 0; r < 4; ++r) O[n][r] = 0.f;
    float m0 = -INFINITY, m1 = -INFINITY, l0 = 0.f, l1 = 0.f;

    const int r0g = qt * 128 + wid * 16 + (lane >> 2);   // this thread's row

    const int ntiles = 2 * qt + 2;
    auto load_kv = [&](int s, int kt) {
        const int kbase = kt * 64;
        #pragma unroll
        for (int j = 0; j < 8; ++j) {
            const int idx = j * 256 + tid;         // 0..2047
            const int arr = idx >> 9;              // 0:kh 1:km 2:vh 3:vm
            const int rem = idx & 511;
            const int row = rem >> 3, c8 = rem & 7;
            const __nv_bfloat16* s4 = (arr == 0) ? Kh : (arr == 1) ? Km
                                     : (arr == 2) ? Vh : Vm;
            cpasync16(sb + s * FA_STGB + arr * FA_ARRB + row * FA_ROWB + c8 * 16,
                      s4 + bhoff + ((size_t)(kbase + row)) * Dh + c8 * 8);
        }
        cp_commit();
    };
    load_kv(0, 0);
    load_kv(1, 1);

    const uint32_t kb_off = ((lane & 7) + ((lane >> 4) & 1) * 8) * FA_ROWB
                            + ((lane >> 3) & 1) * 16;
    const uint32_t v_off  = (lane & 15) * FA_ROWB + (lane >> 4) * 16;

    for (int kt = 0; kt < ntiles; ++kt) {
        const int s = kt & 1;
        if (kt + 2 <= ntiles) cp_wait1(); else cp_wait0();
        __syncthreads();

        const uint32_t kh_b = sb + s * FA_STGB;
        const uint32_t km_b = kh_b + FA_ARRB;
        const uint32_t vh_b = kh_b + 2 * FA_ARRB;
        const uint32_t vm_b = kh_b + 3 * FA_ARRB;

        // ---- S = Qh*Kh + Qm*Kh + Qh*Km (fp32 accum, log2 domain) ----------
        float S[8][4];
        #pragma unroll
        for (int n = 0; n < 8; ++n)
            #pragma unroll
            for (int r = 0; r < 4; ++r) S[n][r] = 0.f;

        #pragma unroll
        for (int ks = 0; ks < 4; ++ks) {
            #pragma unroll
            for (int g = 0; g < 4; ++g) {
                uint32_t b[4];
                ldsm4(b, kh_b + kb_off + g * (16 * FA_ROWB) + ks * 32);
                mma_bf16(S[2 * g],     qhf[ks], b[0], b[1]);
                mma_bf16(S[2 * g + 1], qhf[ks], b[2], b[3]);
                mma_bf16(S[2 * g],     qmf[ks], b[0], b[1]);
                mma_bf16(S[2 * g + 1], qmf[ks], b[2], b[3]);
            }
        }
        #pragma unroll
        for (int ks = 0; ks < 4; ++ks) {
            #pragma unroll
            for (int g = 0; g < 4; ++g) {
                uint32_t b[4];
                ldsm4(b, km_b + kb_off + g * (16 * FA_ROWB) + ks * 32);
                mma_bf16(S[2 * g],     qhf[ks], b[0], b[1]);
                mma_bf16(S[2 * g + 1], qhf[ks], b[2], b[3]);
            }
        }

        // ---- causal mask (only diagonal tiles) -----------------------------
        const int kbase = kt * 64;
        if (kt >= 2 * qt) {
            #pragma unroll
            for (int n = 0; n < 8; ++n) {
                const int col = kbase + n * 8 + (lane & 3) * 2;
                if (col     > r0g)     S[n][0] = -INFINITY;
                if (col + 1 > r0g)     S[n][1] = -INFINITY;
                if (col     > r0g + 8) S[n][2] = -INFINITY;
                if (col + 1 > r0g + 8) S[n][3] = -INFINITY;
            }
        }

        // ---- online softmax (base 2) ---------------------------------------
        float ml0 = -INFINITY, ml1 = -INFINITY;
        #pragma unroll
        for (int n = 0; n < 8; ++n) {
            ml0 = fmaxf(ml0, fmaxf(S[n][0], S[n][1]));
            ml1 = fmaxf(ml1, fmaxf(S[n][2], S[n][3]));
        }
        ml0 = fmaxf(ml0, __shfl_xor_sync(0xFFFFFFFF, ml0, 1));
        ml0 = fmaxf(ml0, __shfl_xor_sync(0xFFFFFFFF, ml0, 2));
        ml1 = fmaxf(ml1, __shfl_xor_sync(0xFFFFFFFF, ml1, 1));
        ml1 = fmaxf(ml1, __shfl_xor_sync(0xFFFFFFFF, ml1, 2));

        const float mn0 = fmaxf(m0, ml0);
        const float mn1 = fmaxf(m1, ml1);
        const float a0 = ex2(m0 - mn0);
        const float a1 = ex2(m1 - mn1);
        m0 = mn0; m1 = mn1;
        l0 *= a0; l1 *= a1;
        #pragma unroll
        for (int n = 0; n < 8; ++n) {
            O[n][0] *= a0; O[n][1] *= a0;
            O[n][2] *= a1; O[n][3] *= a1;
        }
        float sum0 = 0.f, sum1 = 0.f;
        #pragma unroll
        for (int n = 0; n < 8; ++n) {
            S[n][0] = ex2(S[n][0] - mn0); sum0 += S[n][0];
            S[n][1] = ex2(S[n][1] - mn0); sum0 += S[n][1];
            S[n][2] = ex2(S[n][2] - mn1); sum1 += S[n][2];
            S[n][3] = ex2(S[n][3] - mn1); sum1 += S[n][3];
        }
        l0 += sum0; l1 += sum1;

        // ---- O += Ph*Vh + Pm*Vh + Ph*Vm ------------------------------------
        #pragma unroll
        for (int g = 0; g < 4; ++g) {
            uint32_t pa[4], pb[4];
            pack_hm(S[2 * g][0],     S[2 * g][1],     pa[0], pb[0]);
            pack_hm(S[2 * g][2],     S[2 * g][3],     pa[1], pb[1]);
            pack_hm(S[2 * g + 1][0], S[2 * g + 1][1], pa[2], pb[2]);
            pack_hm(S[2 * g + 1][2], S[2 * g + 1][3], pa[3], pb[3]);
            #pragma unroll
            for (int h2 = 0; h2 < 4; ++h2) {
                uint32_t v4[4];
                ldsm4t(v4, vh_b + v_off + g * (16 * FA_ROWB) + h2 * 32);
                mma_bf16(O[2 * h2],     pa, v4[0], v4[1]);
                mma_bf16(O[2 * h2 + 1], pa, v4[2], v4[3]);
                mma_bf16(O[2 * h2],     pb, v4[0], v4[1]);
                mma_bf16(O[2 * h2 + 1], pb, v4[2], v4[3]);
                uint32_t w4[4];
                ldsm4t(w4, vm_b + v_off + g * (16 * FA_ROWB) + h2 * 32);
                mma_bf16(O[2 * h2],     pa, w4[0], w4[1]);
                mma_bf16(O[2 * h2 + 1], pa, w4[2], w4[3]);
            }
        }

        __syncthreads();
        if (kt + 2 < ntiles) load_kv(s, kt + 2);
    }

    // ---- epilogue -----------------------------------------------------------
    l0 += __shfl_xor_sync(0xFFFFFFFF, l0, 1);
    l0 += __shfl_xor_sync(0xFFFFFFFF, l0, 2);
    l1 += __shfl_xor_sync(0xFFFFFFFF, l1, 1);
    l1 += __shfl_xor_sync(0xFFFFFFFF, l1, 2);
    const float inv0 = 1.f / l0, inv1 = 1.f / l1;

    const int b = bh / Hn, h = bh % Hn;
    const size_t base0 = ((size_t)(b * Tlen + r0g)) * Cdim + h * Dh + (lane & 3) * 2;
    const size_t base1 = base0 + (size_t)8 * Cdim;

    #pragma unroll
    for (int n = 0; n < 8; ++n) {
        uint32_t hh, mm;
        pack_hm(O[n][0] * inv0, O[n][1] * inv0, hh, mm);
        *(uint32_t*)(Yh + base0 + n * 8) = hh;
        *(uint32_t*)(Ym + base0 + n * 8) = mm;
        pack_hm(O[n][2] * inv1, O[n][3] * inv1, hh, mm);
        *(uint32_t*)(Yh + base1 + n * 8) = hh;
        *(uint32_t*)(Ym + base1 + n * 8) = mm;
    }
}

// ---------------------------------------------------------------------------
// Launcher
// ---------------------------------------------------------------------------
extern "C" void kernel_launch(void* const* d_in, const int* in_sizes, int n_in,
                              void* d_out, int out_size)
{
    const float* x      = (const float*)d_in[0];
    const float* W_attn = (const float*)d_in[1];
    const float* b_attn = (const float*)d_in[2];
    const float* W_proj = (const float*)d_in[3];
    const float* b_proj = (const float*)d_in[4];
    float* out = (float*)d_out;

    void* p;
    float* qkv;
    __nv_bfloat16 *xh, *xm, *wah, *wam, *wph, *wpm;
    __nv_bfloat16 *qh, *qm, *kh, *km, *vh, *vm, *yh, *ym;
    cudaGetSymbolAddress(&p, g_qkv); qkv = (float*)p;
    cudaGetSymbolAddress(&p, g_xh);  xh  = (__nv_bfloat16*)p;
    cudaGetSymbolAddress(&p, g_xm);  xm  = (__nv_bfloat16*)p;
    cudaGetSymbolAddress(&p, g_wah); wah = (__nv_bfloat16*)p;
    cudaGetSymbolAddress(&p, g_wam); wam = (__nv_bfloat16*)p;
    cudaGetSymbolAddress(&p, g_wph); wph = (__nv_bfloat16*)p;
    cudaGetSymbolAddress(&p, g_wpm); wpm = (__nv_bfloat16*)p;
    cudaGetSymbolAddress(&p, g_qh);  qh  = (__nv_bfloat16*)p;
    cudaGetSymbolAddress(&p, g_qm);  qm  = (__nv_bfloat16*)p;
    cudaGetSymbolAddress(&p, g_kh);  kh  = (__nv_bfloat16*)p;
    cudaGetSymbolAddress(&p, g_km);  km  = (__nv_bfloat16*)p;
    cudaGetSymbolAddress(&p, g_vh);  vh  = (__nv_bfloat16*)p;
    cudaGetSymbolAddress(&p, g_vm);  vm  = (__nv_bfloat16*)p;
    cudaGetSymbolAddress(&p, g_yh);  yh  = (__nv_bfloat16*)p;
    cudaGetSymbolAddress(&p, g_ym);  ym  = (__nv_bfloat16*)p;

    cudaFuncSetAttribute(flash_mma, cudaFuncAttributeMaxDynamicSharedMemorySize,
                         FA_SMEM);

    // prep
    {
        const int n4 = BT * Cdim / 4;
        split_bf16<<<(n4 + 255) / 256, 256>>>((const float4*)x,
            (__nv_bfloat162*)xh, (__nv_bfloat162*)xm, n4);
        dim3 g1(C3 / 32, Kdim / 32);
        trans_split_bf16<<<g1, dim3(32, 8)>>>(W_attn, wah, wam, Kdim, C3);
        dim3 g2(Cdim / 32, Kdim / 32);
        trans_split_bf16<<<g2, dim3(32, 8)>>>(W_proj, wph, wpm, Kdim, Cdim);
    }

    // 1) qkv = x @ W_attn + b_attn
    {
        dim3 grid(C3 / 128, BT / 128);
        gemm_bf16x3<<<grid, 256>>>(xh, xm, wah, wam, b_attn, qkv, C3);
    }

    // 2) RoPE + bf16 hi/mid splits
    {
        const int total = Bsz * Tlen * Hn * (Dh / 2);
        rope_split_bf16<<<(total + 255) / 256, 256>>>(qkv,
            (__nv_bfloat162*)qh, (__nv_bfloat162*)qm,
            (__nv_bfloat162*)kh, (__nv_bfloat162*)km,
            (__nv_bfloat162*)vh, (__nv_bfloat162*)vm);
    }

    // 3) tensor-core causal flash attention -> yh/ym splits
    {
        dim3 grid(8, BH);
        flash_mma<<<grid, 256, FA_SMEM>>>(qh, qm, kh, km, vh, vm, yh, ym);
    }

    // 4) out = y @ W_proj + b_proj
    {
        dim3 grid(Cdim / 128, BT / 128);
        gemm_bf16x3<<<grid, 256>>>(yh, ym, wph, wpm, b_proj, out, Cdim);
    }
}

// round 5
// speedup vs baseline: 3.6444x; 1.1417x over previous
#include <cuda_runtime.h>
#include <cuda_bf16.h>
#include <math.h>
#include <stdint.h>

#define Bsz   8
#define Tlen  1024
#define Cdim  768
#define Hn    12
#define Dh    64
#define BT    (Bsz * Tlen)     // 8192
#define C3    (3 * Cdim)       // 2304
#define BH    (Bsz * Hn)       // 96
#define Kdim  768

// ---------------- scratch (device globals; no cudaMalloc allowed) ----------
__device__ float g_qkv[BT * C3];

__device__ __nv_bfloat16 g_xh[BT * Cdim];
__device__ __nv_bfloat16 g_xm[BT * Cdim];
__device__ __nv_bfloat16 g_wah[C3 * Cdim];
__device__ __nv_bfloat16 g_wam[C3 * Cdim];
__device__ __nv_bfloat16 g_wph[Cdim * Cdim];
__device__ __nv_bfloat16 g_wpm[Cdim * Cdim];

__device__ __nv_bfloat16 g_qh[BH * Tlen * Dh];
__device__ __nv_bfloat16 g_qm[BH * Tlen * Dh];
__device__ __nv_bfloat16 g_kh[BH * Tlen * Dh];
__device__ __nv_bfloat16 g_km[BH * Tlen * Dh];
__device__ __nv_bfloat16 g_vh[BH * Tlen * Dh];
__device__ __nv_bfloat16 g_vm[BH * Tlen * Dh];

__device__ __nv_bfloat16 g_yh[BT * Cdim];
__device__ __nv_bfloat16 g_ym[BT * Cdim];

// ---------------- PTX helpers ----------------------------------------------
__device__ __forceinline__ uint32_t smem_u32(const void* p) {
    uint32_t a;
    asm("{ .reg .u64 t; cvta.to.shared.u64 t, %1; cvt.u32.u64 %0, t; }"
        : "=r"(a) : "l"(p));
    return a;
}
__device__ __forceinline__ void cpasync16(uint32_t dst, const void* src) {
    asm volatile("cp.async.cg.shared.global [%0], [%1], 16;\n" :: "r"(dst), "l"(src));
}
__device__ __forceinline__ void cp_commit() {
    asm volatile("cp.async.commit_group;\n" ::: "memory");
}
__device__ __forceinline__ void cp_wait1() {
    asm volatile("cp.async.wait_group 1;\n" ::: "memory");
}
__device__ __forceinline__ void cp_wait0() {
    asm volatile("cp.async.wait_group 0;\n" ::: "memory");
}
__device__ __forceinline__ void ldsm4(uint32_t (&r)[4], uint32_t addr) {
    asm volatile("ldmatrix.sync.aligned.m8n8.x4.shared.b16 {%0,%1,%2,%3}, [%4];"
        : "=r"(r[0]), "=r"(r[1]), "=r"(r[2]), "=r"(r[3]) : "r"(addr));
}
__device__ __forceinline__ void ldsm4t(uint32_t (&r)[4], uint32_t addr) {
    asm volatile("ldmatrix.sync.aligned.m8n8.x4.trans.shared.b16 {%0,%1,%2,%3}, [%4];"
        : "=r"(r[0]), "=r"(r[1]), "=r"(r[2]), "=r"(r[3]) : "r"(addr));
}
__device__ __forceinline__ void mma_bf16(float (&c)[4], const uint32_t (&a)[4],
                                         uint32_t b0, uint32_t b1) {
    asm volatile(
        "mma.sync.aligned.m16n8k16.row.col.f32.bf16.bf16.f32 "
        "{%0,%1,%2,%3}, {%4,%5,%6,%7}, {%8,%9}, {%0,%1,%2,%3};"
        : "+f"(c[0]), "+f"(c[1]), "+f"(c[2]), "+f"(c[3])
        : "r"(a[0]), "r"(a[1]), "r"(a[2]), "r"(a[3]), "r"(b0), "r"(b1));
}
__device__ __forceinline__ float ex2(float x) {
    float y;
    asm("ex2.approx.f32 %0, %1;" : "=f"(y) : "f"(x));
    return y;
}
__device__ __forceinline__ void pack_hm(float p0, float p1, uint32_t& hi, uint32_t& mid) {
    __nv_bfloat162 h = __floats2bfloat162_rn(p0, p1);
    float r0 = p0 - __bfloat162float(h.x);
    float r1 = p1 - __bfloat162float(h.y);
    __nv_bfloat162 m = __floats2bfloat162_rn(r0, r1);
    hi  = *(uint32_t*)&h;
    mid = *(uint32_t*)&m;
}

// ---------------------------------------------------------------------------
// bf16x3 GEMM v2: C[M, Nt] = A @ Bt^T + bias
// CTA 128x128, 4 warps (warp tile 64x64), K-tile 32, 3-stage cp.async ring,
// one __syncthreads per iteration. 2 CTAs/SM.
// ---------------------------------------------------------------------------
#define GM_NKT   (Kdim / 32)        // 24
#define GM_NIT   (3 * GM_NKT)       // 72
#define ASTR     40                 // bf16 elems per smem row
#define AROWB    (ASTR * 2)         // 80 bytes
#define GM_ATILE (128 * AROWB)      // 10240 bytes
#define GM_STG   (2 * GM_ATILE)     // 20480 bytes (A + B)
#define GM_SMEM  (3 * GM_STG)       // 61440 bytes

__global__ __launch_bounds__(128, 2) void gemm_bf16x3(
    const __nv_bfloat16* __restrict__ A1, const __nv_bfloat16* __restrict__ A2,
    const __nv_bfloat16* __restrict__ B1, const __nv_bfloat16* __restrict__ B2,
    const float* __restrict__ bias, float* __restrict__ C, int Nt)
{
    extern __shared__ __align__(16) char gsm[];
    const uint32_t sb = smem_u32(gsm);
    const int tid  = threadIdx.x;
    const int wid  = tid >> 5;
    const int lane = tid & 31;
    const int wm   = wid & 1;        // 0..1  (64-row half)
    const int wn   = wid >> 1;       // 0..1  (64-col half)
    const int brow = blockIdx.y * 128;
    const int bcol = blockIdx.x * 128;

    const uint32_t a_off =
        (uint32_t)(((wm * 64 + (lane & 15)) * ASTR + (lane >> 4) * 8) * 2);
    const uint32_t b_off =
        (uint32_t)(((wn * 64 + (lane & 7) + ((lane >> 4) & 1) * 8) * ASTR
                    + ((lane >> 3) & 1) * 8) * 2);

    float c[4][8][4];
    #pragma unroll
    for (int i = 0; i < 4; ++i)
        #pragma unroll
        for (int j = 0; j < 8; ++j)
            #pragma unroll
            for (int r = 0; r < 4; ++r) c[i][j][r] = 0.f;

    auto load_stage = [&](int s, int i) {
        const int p  = i / GM_NKT;
        const int k0 = (i % GM_NKT) * 32;
        const __nv_bfloat16* Ap = (p == 1) ? A2 : A1;
        const __nv_bfloat16* Bp = (p == 2) ? B2 : B1;
        const uint32_t ab = sb + s * GM_STG;
        const uint32_t bb = ab + GM_ATILE;
        #pragma unroll
        for (int j = 0; j < 4; ++j) {
            const int idx = j * 128 + tid;          // 0..511
            const int row = idx >> 2, c4 = idx & 3;
            cpasync16(ab + row * AROWB + c4 * 16,
                      Ap + (size_t)(brow + row) * Kdim + k0 + c4 * 8);
            cpasync16(bb + row * AROWB + c4 * 16,
                      Bp + (size_t)(bcol + row) * Kdim + k0 + c4 * 8);
        }
        cp_commit();
    };

    load_stage(0, 0);
    load_stage(1, 1);

    int s = 0;
    for (int i = 0; i < GM_NIT; ++i) {
        if (i < GM_NIT - 1) cp_wait1(); else cp_wait0();
        __syncthreads();
        if (i + 2 < GM_NIT) {
            int s2 = s + 2; if (s2 >= 3) s2 -= 3;
            load_stage(s2, i + 2);
        }

        const uint32_t aB = sb + s * GM_STG + a_off;
        const uint32_t bB = sb + s * GM_STG + GM_ATILE + b_off;
        #pragma unroll
        for (int ks = 0; ks < 2; ++ks) {
            uint32_t a[4][4], b[4][4];
            #pragma unroll
            for (int mt = 0; mt < 4; ++mt)
                ldsm4(a[mt], aB + mt * (16 * AROWB) + ks * 32);
            #pragma unroll
            for (int nt2 = 0; nt2 < 4; ++nt2)
                ldsm4(b[nt2], bB + nt2 * (16 * AROWB) + ks * 32);
            #pragma unroll
            for (int mt = 0; mt < 4; ++mt)
                #pragma unroll
                for (int nt = 0; nt < 8; ++nt)
                    mma_bf16(c[mt][nt], a[mt],
                             b[nt >> 1][(nt & 1) * 2], b[nt >> 1][(nt & 1) * 2 + 1]);
        }
        if (++s == 3) s = 0;
    }

    // epilogue: add bias, store fp32
    #pragma unroll
    for (int mt = 0; mt < 4; ++mt) {
        const int gr = brow + wm * 64 + mt * 16 + (lane >> 2);
        #pragma unroll
        for (int nt = 0; nt < 8; ++nt) {
            const int gc = bcol + wn * 64 + nt * 8 + (lane & 3) * 2;
            const float bx = bias[gc], by = bias[gc + 1];
            float2 o0, o1;
            o0.x = c[mt][nt][0] + bx; o0.y = c[mt][nt][1] + by;
            o1.x = c[mt][nt][2] + bx; o1.y = c[mt][nt][3] + by;
            *(float2*)(C + (size_t)gr * Nt + gc)       = o0;
            *(float2*)(C + (size_t)(gr + 8) * Nt + gc) = o1;
        }
    }
}

// ---------------------------------------------------------------------------
// fp32 -> bf16 hi/mid split
// ---------------------------------------------------------------------------
__global__ void split_bf16(const float4* __restrict__ src,
                           __nv_bfloat162* __restrict__ hi,
                           __nv_bfloat162* __restrict__ mid, int n4)
{
    int i = blockIdx.x * blockDim.x + threadIdx.x;
    if (i >= n4) return;
    float4 v = src[i];
    uint32_t h0, m0, h1, m1;
    pack_hm(v.x, v.y, h0, m0);
    pack_hm(v.z, v.w, h1, m1);
    hi[i * 2]      = *(__nv_bfloat162*)&h0;
    hi[i * 2 + 1]  = *(__nv_bfloat162*)&h1;
    mid[i * 2]     = *(__nv_bfloat162*)&m0;
    mid[i * 2 + 1] = *(__nv_bfloat162*)&m1;
}

// ---------------------------------------------------------------------------
// transpose + bf16 split: W[K][N] -> Th/Tm[N][K]
// ---------------------------------------------------------------------------
__global__ void trans_split_bf16(const float* __restrict__ W,
                                 __nv_bfloat16* __restrict__ Th,
                                 __nv_bfloat16* __restrict__ Tm, int K, int N)
{
    __shared__ float tile[32][33];
    const int kb = blockIdx.y * 32, nb = blockIdx.x * 32;
    const int tx = threadIdx.x, ty = threadIdx.y;
    #pragma unroll
    for (int r = ty; r < 32; r += 8)
        tile[r][tx] = W[(size_t)(kb + r) * N + nb + tx];
    __syncthreads();
    #pragma unroll
    for (int i = ty; i < 32; i += 8) {
        float v = tile[tx][i];
        __nv_bfloat16 h = __float2bfloat16(v);
        __nv_bfloat16 m = __float2bfloat16(v - __bfloat162float(h));
        Th[(size_t)(nb + i) * K + kb + tx] = h;
        Tm[(size_t)(nb + i) * K + kb + tx] = m;
    }
}

// ---------------------------------------------------------------------------
// RoPE + split into bf16 hi/mid. q pre-scaled by 0.125*log2(e).
// ---------------------------------------------------------------------------
#define QSCALE (0.125f * 1.4426950408889634f)

__global__ void rope_split_bf16(const float* __restrict__ qkv,
    __nv_bfloat162* __restrict__ Qh, __nv_bfloat162* __restrict__ Qm,
    __nv_bfloat162* __restrict__ Kh, __nv_bfloat162* __restrict__ Km,
    __nv_bfloat162* __restrict__ Vh, __nv_bfloat162* __restrict__ Vm)
{
    const int total = Bsz * Tlen * Hn * (Dh / 2);
    int idx = blockIdx.x * blockDim.x + threadIdx.x;
    if (idx >= total) return;

    const int i  = idx & 31;
    const int h  = (idx >> 5) % Hn;
    const int bt = idx / (32 * Hn);
    const int t  = bt & (Tlen - 1);

    const float* row = qkv + (size_t)bt * C3;
    const int coff = h * Dh + 2 * i;
    float2 q2 = *(const float2*)(row + coff);
    float2 k2 = *(const float2*)(row + Cdim + coff);
    float2 v2 = *(const float2*)(row + 2 * Cdim + coff);

    const float inv_freq = expf(-(float)i * (9.210340371976184f / 32.0f));
    const float ang = (float)t * inv_freq;
    float s, c;
    sincosf(ang, &s, &c);

    float qx = (q2.x * c - q2.y * s) * QSCALE;
    float qy = (q2.y * c + q2.x * s) * QSCALE;
    float kx = k2.x * c - k2.y * s;
    float ky = k2.y * c + k2.x * s;

    const int bh = (bt >> 10) * Hn + h;
    const size_t o = ((size_t)bh * Tlen + t) * (Dh / 2) + i;

    uint32_t hh, mm;
    pack_hm(qx, qy, hh, mm);
    Qh[o] = *(__nv_bfloat162*)&hh; Qm[o] = *(__nv_bfloat162*)&mm;
    pack_hm(kx, ky, hh, mm);
    Kh[o] = *(__nv_bfloat162*)&hh; Km[o] = *(__nv_bfloat162*)&mm;
    pack_hm(v2.x, v2.y, hh, mm);
    Vh[o] = *(__nv_bfloat162*)&hh; Vm[o] = *(__nv_bfloat162*)&mm;
}

// ---------------------------------------------------------------------------
// Tensor-core causal flash attention (unchanged from R4)
// ---------------------------------------------------------------------------
#define FA_STR   72
#define FA_ROWB  (FA_STR * 2)
#define FA_ARRB  (64 * FA_ROWB)
#define FA_STGB  (4 * FA_ARRB)
#define FA_SMEM  (2 * FA_STGB)

__global__ __launch_bounds__(256, 1) void flash_mma(
    const __nv_bfloat16* __restrict__ Qh, const __nv_bfloat16* __restrict__ Qm,
    const __nv_bfloat16* __restrict__ Kh, const __nv_bfloat16* __restrict__ Km,
    const __nv_bfloat16* __restrict__ Vh, const __nv_bfloat16* __restrict__ Vm,
    __nv_bfloat16* __restrict__ Yh, __nv_bfloat16* __restrict__ Ym)
{
    extern __shared__ __align__(16) char sm_raw[];
    const uint32_t sb = smem_u32(sm_raw);
    const int tid  = threadIdx.x;
    const int wid  = tid >> 5;
    const int lane = tid & 31;
    const int bh   = blockIdx.y;
    const int qt   = 7 - blockIdx.x;
    const size_t bhoff = (size_t)bh * (Tlen * Dh);

    #pragma unroll
    for (int j = 0; j < 8; ++j) {
        const int idx = j * 256 + tid;
        const int arr = idx >> 10;
        const int rem = idx & 1023;
        const int row = rem >> 3, c8 = rem & 7;
        const __nv_bfloat16* s = arr ? Qm : Qh;
        cpasync16(sb + arr * (128 * FA_ROWB) + row * FA_ROWB + c8 * 16,
                  s + bhoff + ((size_t)(qt * 128 + row)) * Dh + c8 * 8);
    }
    cp_commit(); cp_wait0(); __syncthreads();

    uint32_t qhf[4][4], qmf[4][4];
    {
        const uint32_t base =
            sb + ((wid * 16 + (lane & 15)) * FA_STR + (lane >> 4) * 8) * 2;
        #pragma unroll
        for (int ks = 0; ks < 4; ++ks) {
            ldsm4(qhf[ks], base + ks * 32);
            ldsm4(qmf[ks], base + ks * 32 + 128 * FA_ROWB);
        }
    }
    __syncthreads();

    float O[8][4];
    #pragma unroll
    for (int n = 0; n < 8; ++n)
        #pragma unroll
        for (int r = 0; r < 4; ++r) O[n][r] = 0.f;
    float m0 = -INFINITY, m1 = -INFINITY, l0 = 0.f, l1 = 0.f;

    const int r0g = qt * 128 + wid * 16 + (lane >> 2);

    const int ntiles = 2 * qt + 2;
    auto load_kv = [&](int s, int kt) {
        const int kbase = kt * 64;
        #pragma unroll
        for (int j = 0; j < 8; ++j) {
            const int idx = j * 256 + tid;
            const int arr = idx >> 9;
            const int rem = idx & 511;
            const int row = rem >> 3, c8 = rem & 7;
            const __nv_bfloat16* s4 = (arr == 0) ? Kh : (arr == 1) ? Km
                                     : (arr == 2) ? Vh : Vm;
            cpasync16(sb + s * FA_STGB + arr * FA_ARRB + row * FA_ROWB + c8 * 16,
                      s4 + bhoff + ((size_t)(kbase + row)) * Dh + c8 * 8);
        }
        cp_commit();
    };
    load_kv(0, 0);
    load_kv(1, 1);

    const uint32_t kb_off = ((lane & 7) + ((lane >> 4) & 1) * 8) * FA_ROWB
                            + ((lane >> 3) & 1) * 16;
    const uint32_t v_off  = (lane & 15) * FA_ROWB + (lane >> 4) * 16;

    for (int kt = 0; kt < ntiles; ++kt) {
        const int s = kt & 1;
        if (kt + 2 <= ntiles) cp_wait1(); else cp_wait0();
        __syncthreads();

        const uint32_t kh_b = sb + s * FA_STGB;
        const uint32_t km_b = kh_b + FA_ARRB;
        const uint32_t vh_b = kh_b + 2 * FA_ARRB;
        const uint32_t vm_b = kh_b + 3 * FA_ARRB;

        float S[8][4];
        #pragma unroll
        for (int n = 0; n < 8; ++n)
            #pragma unroll
            for (int r = 0; r < 4; ++r) S[n][r] = 0.f;

        #pragma unroll
        for (int ks = 0; ks < 4; ++ks) {
            #pragma unroll
            for (int g = 0; g < 4; ++g) {
                uint32_t b[4];
                ldsm4(b, kh_b + kb_off + g * (16 * FA_ROWB) + ks * 32);
                mma_bf16(S[2 * g],     qhf[ks], b[0], b[1]);
                mma_bf16(S[2 * g + 1], qhf[ks], b[2], b[3]);
                mma_bf16(S[2 * g],     qmf[ks], b[0], b[1]);
                mma_bf16(S[2 * g + 1], qmf[ks], b[2], b[3]);
            }
        }
        #pragma unroll
        for (int ks = 0; ks < 4; ++ks) {
            #pragma unroll
            for (int g = 0; g < 4; ++g) {
                uint32_t b[4];
                ldsm4(b, km_b + kb_off + g * (16 * FA_ROWB) + ks * 32);
                mma_bf16(S[2 * g],     qhf[ks], b[0], b[1]);
                mma_bf16(S[2 * g + 1], qhf[ks], b[2], b[3]);
            }
        }

        const int kbase = kt * 64;
        if (kt >= 2 * qt) {
            #pragma unroll
            for (int n = 0; n < 8; ++n) {
                const int col = kbase + n * 8 + (lane & 3) * 2;
                if (col     > r0g)     S[n][0] = -INFINITY;
                if (col + 1 > r0g)     S[n][1] = -INFINITY;
                if (col     > r0g + 8) S[n][2] = -INFINITY;
                if (col + 1 > r0g + 8) S[n][3] = -INFINITY;
            }
        }

        float ml0 = -INFINITY, ml1 = -INFINITY;
        #pragma unroll
        for (int n = 0; n < 8; ++n) {
            ml0 = fmaxf(ml0, fmaxf(S[n][0], S[n][1]));
            ml1 = fmaxf(ml1, fmaxf(S[n][2], S[n][3]));
        }
        ml0 = fmaxf(ml0, __shfl_xor_sync(0xFFFFFFFF, ml0, 1));
        ml0 = fmaxf(ml0, __shfl_xor_sync(0xFFFFFFFF, ml0, 2));
        ml1 = fmaxf(ml1, __shfl_xor_sync(0xFFFFFFFF, ml1, 1));
        ml1 = fmaxf(ml1, __shfl_xor_sync(0xFFFFFFFF, ml1, 2));

        const float mn0 = fmaxf(m0, ml0);
        const float mn1 = fmaxf(m1, ml1);
        const float a0 = ex2(m0 - mn0);
        const float a1 = ex2(m1 - mn1);
        m0 = mn0; m1 = mn1;
        l0 *= a0; l1 *= a1;
        #pragma unroll
        for (int n = 0; n < 8; ++n) {
            O[n][0] *= a0; O[n][1] *= a0;
            O[n][2] *= a1; O[n][3] *= a1;
        }
        float sum0 = 0.f, sum1 = 0.f;
        #pragma unroll
        for (int n = 0; n < 8; ++n) {
            S[n][0] = ex2(S[n][0] - mn0); sum0 += S[n][0];
            S[n][1] = ex2(S[n][1] - mn0); sum0 += S[n][1];
            S[n][2] = ex2(S[n][2] - mn1); sum1 += S[n][2];
            S[n][3] = ex2(S[n][3] - mn1); sum1 += S[n][3];
        }
        l0 += sum0; l1 += sum1;

        #pragma unroll
        for (int g = 0; g < 4; ++g) {
            uint32_t pa[4], pb[4];
            pack_hm(S[2 * g][0],     S[2 * g][1],     pa[0], pb[0]);
            pack_hm(S[2 * g][2],     S[2 * g][3],     pa[1], pb[1]);
            pack_hm(S[2 * g + 1][0], S[2 * g + 1][1], pa[2], pb[2]);
            pack_hm(S[2 * g + 1][2], S[2 * g + 1][3], pa[3], pb[3]);
            #pragma unroll
            for (int h2 = 0; h2 < 4; ++h2) {
                uint32_t v4[4];
                ldsm4t(v4, vh_b + v_off + g * (16 * FA_ROWB) + h2 * 32);
                mma_bf16(O[2 * h2],     pa, v4[0], v4[1]);
                mma_bf16(O[2 * h2 + 1], pa, v4[2], v4[3]);
                mma_bf16(O[2 * h2],     pb, v4[0], v4[1]);
                mma_bf16(O[2 * h2 + 1], pb, v4[2], v4[3]);
                uint32_t w4[4];
                ldsm4t(w4, vm_b + v_off + g * (16 * FA_ROWB) + h2 * 32);
                mma_bf16(O[2 * h2],     pa, w4[0], w4[1]);
                mma_bf16(O[2 * h2 + 1], pa, w4[2], w4[3]);
            }
        }

        __syncthreads();
        if (kt + 2 < ntiles) load_kv(s, kt + 2);
    }

    l0 += __shfl_xor_sync(0xFFFFFFFF, l0, 1);
    l0 += __shfl_xor_sync(0xFFFFFFFF, l0, 2);
    l1 += __shfl_xor_sync(0xFFFFFFFF, l1, 1);
    l1 += __shfl_xor_sync(0xFFFFFFFF, l1, 2);
    const float inv0 = 1.f / l0, inv1 = 1.f / l1;

    const int b = bh / Hn, h = bh % Hn;
    const size_t base0 = ((size_t)(b * Tlen + r0g)) * Cdim + h * Dh + (lane & 3) * 2;
    const size_t base1 = base0 + (size_t)8 * Cdim;

    #pragma unroll
    for (int n = 0; n < 8; ++n) {
        uint32_t hh, mm;
        pack_hm(O[n][0] * inv0, O[n][1] * inv0, hh, mm);
        *(uint32_t*)(Yh + base0 + n * 8) = hh;
        *(uint32_t*)(Ym + base0 + n * 8) = mm;
        pack_hm(O[n][2] * inv1, O[n][3] * inv1, hh, mm);
        *(uint32_t*)(Yh + base1 + n * 8) = hh;
        *(uint32_t*)(Ym + base1 + n * 8) = mm;
    }
}

// ---------------------------------------------------------------------------
// Launcher
// ---------------------------------------------------------------------------
extern "C" void kernel_launch(void* const* d_in, const int* in_sizes, int n_in,
                              void* d_out, int out_size)
{
    const float* x      = (const float*)d_in[0];
    const float* W_attn = (const float*)d_in[1];
    const float* b_attn = (const float*)d_in[2];
    const float* W_proj = (const float*)d_in[3];
    const float* b_proj = (const float*)d_in[4];
    float* out = (float*)d_out;

    void* p;
    float* qkv;
    __nv_bfloat16 *xh, *xm, *wah, *wam, *wph, *wpm;
    __nv_bfloat16 *qh, *qm, *kh, *km, *vh, *vm, *yh, *ym;
    cudaGetSymbolAddress(&p, g_qkv); qkv = (float*)p;
    cudaGetSymbolAddress(&p, g_xh);  xh  = (__nv_bfloat16*)p;
    cudaGetSymbolAddress(&p, g_xm);  xm  = (__nv_bfloat16*)p;
    cudaGetSymbolAddress(&p, g_wah); wah = (__nv_bfloat16*)p;
    cudaGetSymbolAddress(&p, g_wam); wam = (__nv_bfloat16*)p;
    cudaGetSymbolAddress(&p, g_wph); wph = (__nv_bfloat16*)p;
    cudaGetSymbolAddress(&p, g_wpm); wpm = (__nv_bfloat16*)p;
    cudaGetSymbolAddress(&p, g_qh);  qh  = (__nv_bfloat16*)p;
    cudaGetSymbolAddress(&p, g_qm);  qm  = (__nv_bfloat16*)p;
    cudaGetSymbolAddress(&p, g_kh);  kh  = (__nv_bfloat16*)p;
    cudaGetSymbolAddress(&p, g_km);  km  = (__nv_bfloat16*)p;
    cudaGetSymbolAddress(&p, g_vh);  vh  = (__nv_bfloat16*)p;
    cudaGetSymbolAddress(&p, g_vm);  vm  = (__nv_bfloat16*)p;
    cudaGetSymbolAddress(&p, g_yh);  yh  = (__nv_bfloat16*)p;
    cudaGetSymbolAddress(&p, g_ym);  ym  = (__nv_bfloat16*)p;

    cudaFuncSetAttribute(gemm_bf16x3, cudaFuncAttributeMaxDynamicSharedMemorySize,
                         GM_SMEM);
    cudaFuncSetAttribute(flash_mma, cudaFuncAttributeMaxDynamicSharedMemorySize,
                         FA_SMEM);

    // prep
    {
        const int n4 = BT * Cdim / 4;
        split_bf16<<<(n4 + 255) / 256, 256>>>((const float4*)x,
            (__nv_bfloat162*)xh, (__nv_bfloat162*)xm, n4);
        dim3 g1(C3 / 32, Kdim / 32);
        trans_split_bf16<<<g1, dim3(32, 8)>>>(W_attn, wah, wam, Kdim, C3);
        dim3 g2(Cdim / 32, Kdim / 32);
        trans_split_bf16<<<g2, dim3(32, 8)>>>(W_proj, wph, wpm, Kdim, Cdim);
    }

    // 1) qkv = x @ W_attn + b_attn
    {
        dim3 grid(C3 / 128, BT / 128);
        gemm_bf16x3<<<grid, 128, GM_SMEM>>>(xh, xm, wah, wam, b_attn, qkv, C3);
    }

    // 2) RoPE + bf16 hi/mid splits
    {
        const int total = Bsz * Tlen * Hn * (Dh / 2);
        rope_split_bf16<<<(total + 255) / 256, 256>>>(qkv,
            (__nv_bfloat162*)qh, (__nv_bfloat162*)qm,
            (__nv_bfloat162*)kh, (__nv_bfloat162*)km,
            (__nv_bfloat162*)vh, (__nv_bfloat162*)vm);
    }

    // 3) tensor-core causal flash attention -> yh/ym splits
    {
        dim3 grid(8, BH);
        flash_mma<<<grid, 256, FA_SMEM>>>(qh, qm, kh, km, vh, vm, yh, ym);
    }

    // 4) out = y @ W_proj + b_proj
    {
        dim3 grid(Cdim / 128, BT / 128);
        gemm_bf16x3<<<grid, 128, GM_SMEM>>>(yh, ym, wph, wpm, b_proj, out, Cdim);
    }
}